// round 5
// baseline (speedup 1.0000x reference)
#include <cuda_runtime.h>
#include <cuda_bf16.h>

// Seesaw loss, collapsed form:
//   denom[b] = sum_{j != t} s[t,j]*exp(l[b,j]) + exp(l[b,t])
//   loss[b]  = -log( exp(l[b,t]) / (denom + eps) + eps )
//   out      = mean_b loss[b]
// Shift-invariance of sigma makes row-max subtraction unnecessary.
//
// R5 changes vs R4:
//  - single fused kernel: tail-block (ticket-counter) reduction replaces the
//    second launch, which sat at a ~5us overhead floor (0.0% DRAM util)
//  - load qualifiers reverted to R3 (fastest measured row kernel)
//  - counter self-resets -> deterministic and graph-replayable

#define C_CLASSES 1604
#define C_VEC (C_CLASSES / 4)   // 401 float4 per row
#define WARPS_PER_BLOCK 8
#define MAX_BLOCKS 4096
#define EPS 1e-6f

__device__ float g_block[MAX_BLOCKS];
__device__ unsigned int g_ticket;   // zero-initialized at load; reset each run

__global__ __launch_bounds__(WARPS_PER_BLOCK * 32)
void seesaw_fused_kernel(const float* __restrict__ logits,
                         const float* __restrict__ s,
                         const int* __restrict__ targets,
                         float* __restrict__ out,
                         int B) {
    __shared__ float sh_loss[WARPS_PER_BLOCK];
    __shared__ bool  sh_last;
    const int warp = threadIdx.x >> 5;
    const int lane = threadIdx.x & 31;
    const int b = blockIdx.x * WARPS_PER_BLOCK + warp;

    float loss = 0.0f;
    if (b < B) {
        const int t = targets[b];
        const float4* __restrict__ lrow = (const float4*)(logits + (size_t)b * C_CLASSES);
        const float4* __restrict__ wrow = (const float4*)(s + (size_t)t * C_CLASSES);

        float acc = 0.0f;
        #pragma unroll 4
        for (int v = lane; v < C_VEC; v += 32) {
            float4 l = lrow[v];
            float4 w = wrow[v];
            acc = fmaf(w.x, __expf(l.x), acc);
            acc = fmaf(w.y, __expf(l.y), acc);
            acc = fmaf(w.z, __expf(l.z), acc);
            acc = fmaf(w.w, __expf(l.w), acc);
        }

        #pragma unroll
        for (int off = 16; off > 0; off >>= 1)
            acc += __shfl_xor_sync(0xFFFFFFFFu, acc, off);

        if (lane == 0) {
            float lt  = logits[(size_t)b * C_CLASSES + t];
            float et  = __expf(lt);
            float wtt = s[(size_t)t * C_CLASSES + t];
            float denom = acc - wtt * et + et;   // swap j==t weighted term for plain e^lt
            float sigma = et / (denom + EPS);
            loss = -logf(sigma + EPS);
        }
    }
    if (lane == 0) sh_loss[warp] = loss;
    __syncthreads();

    // warp 0 folds the block's 8 row-losses into one partial, publishes it,
    // and takes a ticket
    if (warp == 0) {
        float v = (lane < WARPS_PER_BLOCK) ? sh_loss[lane] : 0.0f;
        #pragma unroll
        for (int off = 4; off > 0; off >>= 1)
            v += __shfl_xor_sync(0xFFFFFFFFu, v, off);
        if (lane == 0) {
            g_block[blockIdx.x] = v;
            __threadfence();
            unsigned int t = atomicAdd(&g_ticket, 1u);
            sh_last = (t == gridDim.x - 1);
        }
    }
    __syncthreads();

    // last-arriving block reduces all partials (fixed order -> deterministic)
    if (sh_last) {
        __shared__ float sh[WARPS_PER_BLOCK];
        const int nblocks = gridDim.x;
        float acc = 0.0f;
        const float4* p4 = (const float4*)g_block;
        const int nvec = nblocks >> 2;
        for (int i = threadIdx.x; i < nvec; i += WARPS_PER_BLOCK * 32) {
            float4 v = p4[i];
            acc += v.x + v.y + v.z + v.w;
        }
        for (int i = (nvec << 2) + threadIdx.x; i < nblocks; i += WARPS_PER_BLOCK * 32)
            acc += g_block[i];

        #pragma unroll
        for (int off = 16; off > 0; off >>= 1)
            acc += __shfl_xor_sync(0xFFFFFFFFu, acc, off);
        if (lane == 0) sh[warp] = acc;
        __syncthreads();
        if (warp == 0) {
            float v = (lane < WARPS_PER_BLOCK) ? sh[lane] : 0.0f;
            #pragma unroll
            for (int off = 4; off > 0; off >>= 1)
                v += __shfl_xor_sync(0xFFFFFFFFu, v, off);
            if (lane == 0) {
                out[0] = v / (float)B;
                g_ticket = 0;   // reset for next graph replay
            }
        }
    }
}

extern "C" void kernel_launch(void* const* d_in, const int* in_sizes, int n_in,
                              void* d_out, int out_size) {
    const float* logits  = (const float*)d_in[0];   // [B, C] f32
    const float* s       = (const float*)d_in[1];   // [C, C] f32
    const int*   targets = (const int*)d_in[2];     // [B] int32
    float* out = (float*)d_out;

    const int B = in_sizes[2];
    const int grid = (B + WARPS_PER_BLOCK - 1) / WARPS_PER_BLOCK;

    seesaw_fused_kernel<<<grid, WARPS_PER_BLOCK * 32>>>(logits, s, targets, out, B);
}